// round 5
// baseline (speedup 1.0000x reference)
#include <cuda_runtime.h>
#include <cuda_bf16.h>

// KANStressPredictor: elementwise map over [B, T, 3] f32 strain.
//   c00 = 2*s0+1, c11 = 2*s1+1, c01 = s2
//   det = c00*c11 - c01^2 ;  L = log2(det)
//   mean = 0.5*(c00+c11) ;  rad = sqrt(0.25*(c00-c11)^2 + c01^2)
//   lam1 = mean+rad ;  log2(lam0) = L - log2(lam1)   [lam0*lam1 = det]
//   out_i = exp2( ki0*0.5*log2(lam_i) - ki0*L/6 ) ;  out_2 = 0.5*ln2*ki1*L
//
// R5: R4 pipeline with the cp.async destination-offset bug fixed
// (dst offsets were tid/+512/+1024 against src tid/+256/+512 — smem slots
// 256..511 stale, writes spilled into the peer buffer -> rel_err 0.13).

#define LN2_F 0.6931471805599453f
#define TILE_F4 768           // float4 per tile = 3072 floats = 1024 groups
#define THREADS 256
#define GRID_BLOCKS 888       // 148 SMs x 6 resident blocks (36KB smem each)

__device__ __forceinline__ float ex2_approx(float x) {
    float r;
    asm("ex2.approx.ftz.f32 %0, %1;" : "=f"(r) : "f"(x));
    return r;
}

__device__ __forceinline__ unsigned smem_u32(const void* p) {
    return (unsigned)__cvta_generic_to_shared(p);
}

__device__ __forceinline__ void cp_async16(unsigned dst, const void* src) {
    asm volatile("cp.async.cg.shared.global [%0], [%1], 16;" :: "r"(dst), "l"(src));
}

__device__ __forceinline__ void stage_tile(unsigned dst_base, const float4* src, int tid) {
    // coalesced: 3 phases of lane-stride-1 float4, dst offset == src offset
    cp_async16(dst_base + (tid      ) * 16, src + tid      );
    cp_async16(dst_base + (tid + 256) * 16, src + tid + 256);
    cp_async16(dst_base + (tid + 512) * 16, src + tid + 512);
}

__device__ __forceinline__ void kan_group(float s0, float s1, float s2,
                                          float ki0h, float ki0_6, float k1s,
                                          float& o0, float& o1, float& o2) {
    float c00 = fmaf(2.0f, s0, 1.0f);
    float c11 = fmaf(2.0f, s1, 1.0f);
    float c01 = s2;

    float det  = fmaf(c00, c11, -c01 * c01);
    float L    = __log2f(det);

    float mean = 0.5f * (c00 + c11);
    float diff = 0.5f * (c00 - c11);
    float rad  = __fsqrt_rn(fmaf(diff, diff, c01 * c01));

    float lam1 = mean + rad;                 // larger eigenvalue
    float lg1  = __log2f(lam1);
    float lg0  = L - lg1;                    // log2(lam0) for free

    float base = ki0_6 * L;
    o0 = ex2_approx(fmaf(ki0h, lg0, -base));
    o1 = ex2_approx(fmaf(ki0h, lg1, -base));
    o2 = k1s * L;
}

__global__ void __launch_bounds__(THREADS)
kan_stress_pipe_kernel(const float4* __restrict__ in, float4* __restrict__ out,
                       const float* __restrict__ ki0p, const float* __restrict__ ki1p,
                       long long n_tiles) {
    __shared__ float4 s_in[2][TILE_F4];
    __shared__ float4 s_out[TILE_F4];

    int tid = threadIdx.x;
    long long tile0 = blockIdx.x;
    long long stride = gridDim.x;

    float ki0 = __ldg(ki0p);
    float ki1 = __ldg(ki1p);
    float ki0h  = 0.5f * ki0;
    float ki0_6 = ki0 * (1.0f / 6.0f);
    float k1s   = 0.5f * LN2_F * ki1;

    if (tile0 >= n_tiles) return;

    unsigned s_in_base[2] = { smem_u32(&s_in[0][0]), smem_u32(&s_in[1][0]) };

    // prologue: prefetch first tile into buffer 0
    stage_tile(s_in_base[0], in + tile0 * TILE_F4, tid);
    asm volatile("cp.async.commit_group;");

    int buf = 0;
    for (long long tile = tile0; tile < n_tiles; tile += stride) {
        long long nxt = tile + stride;
        if (nxt < n_tiles) {
            // prefetch next tile into the other buffer (in flight during compute)
            stage_tile(s_in_base[buf ^ 1], in + nxt * TILE_F4, tid);
            asm volatile("cp.async.commit_group;");
            asm volatile("cp.async.wait_group 1;");   // current tile complete
        } else {
            asm volatile("cp.async.wait_group 0;");
        }
        __syncthreads();   // all threads' cp.asyncs for this tile visible

        // stride-3 float4 gather in smem: conflict-free
        const float4* sb = s_in[buf];
        float4 a = sb[3 * tid + 0];
        float4 b = sb[3 * tid + 1];
        float4 c = sb[3 * tid + 2];

        float4 ra, rb, rc;
        kan_group(a.x, a.y, a.z, ki0h, ki0_6, k1s, ra.x, ra.y, ra.z);
        kan_group(a.w, b.x, b.y, ki0h, ki0_6, k1s, ra.w, rb.x, rb.y);
        kan_group(b.z, b.w, c.x, ki0h, ki0_6, k1s, rb.z, rb.w, rc.x);
        kan_group(c.y, c.z, c.w, ki0h, ki0_6, k1s, rc.y, rc.z, rc.w);

        s_out[3 * tid + 0] = ra;
        s_out[3 * tid + 1] = rb;
        s_out[3 * tid + 2] = rc;

        __syncthreads();   // STS complete before coalesced read-out

        float4* dst = out + tile * TILE_F4;
        dst[tid      ] = s_out[tid      ];
        dst[tid + 256] = s_out[tid + 256];
        dst[tid + 512] = s_out[tid + 512];

        buf ^= 1;
        // no barrier needed here: iter i's s_in reads precede its sync2;
        // iter i+1's cp.async into that buffer comes after sync2. s_out
        // reads are per-thread complete before that thread's next STS,
        // and cross-thread ordered by the next iteration's sync1.
    }
}

// Scalar fallback for groups beyond the last full tile.
__global__ void kan_stress_tail_kernel(const float* __restrict__ in, float* __restrict__ out,
                                       const float* __restrict__ ki0p, const float* __restrict__ ki1p,
                                       long long g0, long long n_groups) {
    long long g = g0 + blockIdx.x * (long long)blockDim.x + threadIdx.x;
    if (g >= n_groups) return;

    float ki0 = __ldg(ki0p);
    float ki1 = __ldg(ki1p);
    float ki0h  = 0.5f * ki0;
    float ki0_6 = ki0 * (1.0f / 6.0f);
    float k1s   = 0.5f * LN2_F * ki1;

    float s0 = in[3 * g + 0];
    float s1 = in[3 * g + 1];
    float s2 = in[3 * g + 2];
    float o0, o1, o2;
    kan_group(s0, s1, s2, ki0h, ki0_6, k1s, o0, o1, o2);
    out[3 * g + 0] = o0;
    out[3 * g + 1] = o1;
    out[3 * g + 2] = o2;
}

extern "C" void kernel_launch(void* const* d_in, const int* in_sizes, int n_in,
                              void* d_out, int out_size) {
    const float* strain = (const float*)d_in[0];
    const float* ki0    = (const float*)d_in[1];
    const float* ki1    = (const float*)d_in[2];
    float* out          = (float*)d_out;

    long long total_floats = in_sizes[0];
    long long n_groups = total_floats / 3;
    long long n_tiles  = n_groups / 1024;    // 1024 groups per tile

    if (n_tiles > 0) {
        int grid = (int)(n_tiles < GRID_BLOCKS ? n_tiles : GRID_BLOCKS);
        kan_stress_pipe_kernel<<<grid, THREADS>>>(
            (const float4*)strain, (float4*)out, ki0, ki1, n_tiles);
    }
    long long done = n_tiles * 1024;
    long long rem = n_groups - done;
    if (rem > 0) {
        int block = 256;
        int grid = (int)((rem + block - 1) / block);
        kan_stress_tail_kernel<<<grid, block>>>(strain, out, ki0, ki1, done, n_groups);
    }
}

// round 7
// speedup vs baseline: 1.1105x; 1.1105x over previous
#include <cuda_runtime.h>
#include <cuda_bf16.h>

// KANStressPredictor: elementwise map over [B, T, 3] f32 strain.
//   c00 = 2*s0+1, c11 = 2*s1+1, c01 = s2
//   det = c00*c11 - c01^2 ;  L = log2(det)
//   mean = 0.5*(c00+c11) ;  rad = sqrt(0.25*(c00-c11)^2 + c01^2)
//   lam1 = mean+rad ;  log2(lam0) = L - log2(lam1)   [lam0*lam1 = det]
//   out_i = exp2( ki0*0.5*log2(lam_i) - ki0*L/6 ) ;  out_2 = 0.5*ln2*ki1*L
//
// R7: R6 overlapping-window kernel with the r==1 routing bug fixed
// (a2 must be L1.y = f5, not L1.x = f4).
//
// Mapping (re-derived, j = 3m + r; output floats 4j..4j+3):
//  r=0: s=3m   window f0..f5 = L0.xyzw,L1.xy ; A=f0f1f2 B=f3f4f5 ; out=A0A1A2B0
//  r=1: s=3m   A = f3,f4,f5 = L0.w,L1.x,L1.y ; B = f6,f7,f8 = L1.z,L1.w,f8
//              out = A1,A2,B0,B1
//  r=2: s=3m+1 A = L0.z,L0.w,L1.x ; B = L1.y,L1.z,L1.w ; out = A2,B0,B1,B2

#define LN2_F 0.6931471805599453f

__device__ __forceinline__ float ex2_approx(float x) {
    float r;
    asm("ex2.approx.ftz.f32 %0, %1;" : "=f"(r) : "f"(x));
    return r;
}

__device__ __forceinline__ void kan_group(float s0, float s1, float s2,
                                          float ki0h, float ki0_6, float k1s,
                                          float& o0, float& o1, float& o2) {
    float c00 = fmaf(2.0f, s0, 1.0f);
    float c11 = fmaf(2.0f, s1, 1.0f);
    float c01 = s2;

    float det  = fmaf(c00, c11, -c01 * c01);
    float L    = __log2f(det);

    float mean = 0.5f * (c00 + c11);
    float diff = 0.5f * (c00 - c11);
    float rad  = __fsqrt_rn(fmaf(diff, diff, c01 * c01));

    float lam1 = mean + rad;                 // larger eigenvalue
    float lg1  = __log2f(lam1);
    float lg0  = L - lg1;                    // log2(lam0) for free

    float base = ki0_6 * L;
    o0 = ex2_approx(fmaf(ki0h, lg0, -base));
    o1 = ex2_approx(fmaf(ki0h, lg1, -base));
    o2 = k1s * L;
}

__global__ void __launch_bounds__(256)
kan_stress_window_kernel(const float4* __restrict__ in, float4* __restrict__ out,
                         const float* __restrict__ ki0p, const float* __restrict__ ki1p,
                         int n_out_f4, long long total_floats) {
    int j = blockIdx.x * blockDim.x + threadIdx.x;
    if (j >= n_out_f4) return;

    int m = j / 3;
    int r = j - 3 * m;            // 0,1,2

    int s = 3 * m + (r == 2 ? 1 : 0);

    // 2 coalesced/overlapping float4 loads + 1 scalar (consumed only when r==1)
    float4 L0 = in[s];
    float4 L1 = in[s + 1];
    long long sc_idx = 4LL * s + 8;
    if (sc_idx >= total_floats) sc_idx = 0;     // value unused when clamped
    float f8 = __ldg(((const float*)in) + sc_idx);

    float ki0 = __ldg(ki0p);
    float ki1 = __ldg(ki1p);
    float ki0h  = 0.5f * ki0;
    float ki0_6 = ki0 * (1.0f / 6.0f);
    float k1s   = 0.5f * LN2_F * ki1;

    bool r0 = (r == 0), r1 = (r == 1);
    // group A inputs
    float a0 = r0 ? L0.x : (r1 ? L0.w : L0.z);
    float a1 = r0 ? L0.y : (r1 ? L1.x : L0.w);
    float a2 = r0 ? L0.z : (r1 ? L1.y : L1.x);   // FIXED: r==1 -> L1.y (f5)
    // group B inputs
    float b0 = r0 ? L0.w : (r1 ? L1.z : L1.y);
    float b1 = r0 ? L1.x : (r1 ? L1.w : L1.z);
    float b2 = r0 ? L1.y : (r1 ? f8   : L1.w);

    float A0, A1, A2, B0, B1, B2;
    kan_group(a0, a1, a2, ki0h, ki0_6, k1s, A0, A1, A2);
    kan_group(b0, b1, b2, ki0h, ki0_6, k1s, B0, B1, B2);

    // output chain C = {A0,A1,A2,B0,B1,B2}, out.k = C[r+k]
    float4 o;
    o.x = r0 ? A0 : (r1 ? A1 : A2);
    o.y = r0 ? A1 : (r1 ? A2 : B0);
    o.z = r0 ? A2 : (r1 ? B0 : B1);
    o.w = r0 ? B0 : (r1 ? B1 : B2);

    out[j] = o;
}

// Scalar fallback for trailing floats not covered by float4 slots
// (defensive; unused for the benchmarked 4096x2048x3 shape).
__global__ void kan_stress_tail_kernel(const float* __restrict__ in, float* __restrict__ out,
                                       const float* __restrict__ ki0p, const float* __restrict__ ki1p,
                                       long long g0, long long n_groups) {
    long long g = g0 + blockIdx.x * (long long)blockDim.x + threadIdx.x;
    if (g >= n_groups) return;

    float ki0 = __ldg(ki0p);
    float ki1 = __ldg(ki1p);
    float ki0h  = 0.5f * ki0;
    float ki0_6 = ki0 * (1.0f / 6.0f);
    float k1s   = 0.5f * LN2_F * ki1;

    float s0 = in[3 * g + 0];
    float s1 = in[3 * g + 1];
    float s2 = in[3 * g + 2];
    float o0, o1, o2;
    kan_group(s0, s1, s2, ki0h, ki0_6, k1s, o0, o1, o2);
    out[3 * g + 0] = o0;
    out[3 * g + 1] = o1;
    out[3 * g + 2] = o2;
}

extern "C" void kernel_launch(void* const* d_in, const int* in_sizes, int n_in,
                              void* d_out, int out_size) {
    const float* strain = (const float*)d_in[0];
    const float* ki0    = (const float*)d_in[1];
    const float* ki1    = (const float*)d_in[2];
    float* out          = (float*)d_out;

    long long total_floats = in_sizes[0];     // B*T*3 (also out_size)
    long long n_out_f4 = total_floats / 4;    // full float4 slots (exact for bench shape)

    if (n_out_f4 > 0) {
        int block = 256;
        int grid = (int)((n_out_f4 + block - 1) / block);
        kan_stress_window_kernel<<<grid, block>>>(
            (const float4*)strain, (float4*)out, ki0, ki1,
            (int)n_out_f4, total_floats);
    }

    // floats beyond 4*n_out_f4 (total%4) belong to the last 1-2 groups.
    long long floats_done = n_out_f4 * 4;
    if (floats_done < total_floats) {
        long long g0 = floats_done / 3;       // first group touching the tail
        long long n_groups = total_floats / 3;
        long long rem = n_groups - g0;
        if (rem > 0) {
            int block = 128;
            int grid = (int)((rem + block - 1) / block);
            kan_stress_tail_kernel<<<grid, block>>>(strain, out, ki0, ki1, g0, n_groups);
        }
    }
}

// round 8
// speedup vs baseline: 1.1978x; 1.0786x over previous
#include <cuda_runtime.h>
#include <cuda_bf16.h>

// KANStressPredictor: elementwise map over [B, T, 3] f32 strain.
// Group math (s0,s1,s2):
//   mean = s0+s1+1 ;  rad = sqrt((s0-s1)^2 + s2^2)     [= eigen radius of C]
//   lam0 = mean-rad, lam1 = mean+rad                    [eigenvalues of C]
//   lg_i = log2(lam_i) ;  L = lg0+lg1 = log2(det C)
//   out_i = exp2( ki0*0.5*lg_i - ki0*L/6 ) ;  out_2 = 0.5*ln2*ki1 * L
//
// R8: exact float2 scheme. R7 was issue-bound (67%, 1.5x redundant compute +
// 20 sels/thread). Here thread t owns floats 6t..6t+5 = EXACTLY groups
// 2t,2t+1: 2 overlapping LDG.128 (s=(3t)>>1, parity-only routing, 6 sels),
// zero redundant compute, stores in natural order as 3 STG.64 (no sels).
// Trades store coalescing (L1 43% had headroom) for -38% instructions.

#define LN2_F 0.6931471805599453f

__device__ __forceinline__ float ex2_approx(float x) {
    float r;
    asm("ex2.approx.ftz.f32 %0, %1;" : "=f"(r) : "f"(x));
    return r;
}

__device__ __forceinline__ void kan_group(float s0, float s1, float s2,
                                          float ki0h, float ki0_6, float k1s,
                                          float& o0, float& o1, float& o2) {
    float mean = s0 + s1 + 1.0f;               // 0.5*(c00+c11)
    float diff = s0 - s1;                      // 0.5*(c00-c11)
    float rad  = __fsqrt_rn(fmaf(diff, diff, s2 * s2));

    float lam0 = mean - rad;                   // rad < 0.3*mean: no cancellation
    float lam1 = mean + rad;
    float lg0  = __log2f(lam0);
    float lg1  = __log2f(lam1);
    float L    = lg0 + lg1;                    // log2(det)

    float base = ki0_6 * L;
    o0 = ex2_approx(fmaf(ki0h, lg0, -base));
    o1 = ex2_approx(fmaf(ki0h, lg1, -base));
    o2 = k1s * L;
}

__global__ void __launch_bounds__(256)
kan_stress_f2_kernel(const float4* __restrict__ in, float2* __restrict__ out2,
                     const float* __restrict__ ki0p, const float* __restrict__ ki1p,
                     int n_threads) {
    int t = blockIdx.x * blockDim.x + threadIdx.x;
    if (t >= n_threads) return;

    int s = (3 * t) >> 1;
    bool odd = (t & 1) != 0;

    // floats 6t..6t+5 live in f4 slots s, s+1 at offset 2*(t&1):
    //  even t: w0..w5 = L0.x y z w, L1.x y
    //  odd  t: w0..w5 = L0.z w, L1.x y z w
    float4 L0 = in[s];
    float4 L1 = in[s + 1];

    float a0 = odd ? L0.z : L0.x;
    float a1 = odd ? L0.w : L0.y;
    float a2 = odd ? L1.x : L0.z;
    float b0 = odd ? L1.y : L0.w;
    float b1 = odd ? L1.z : L1.x;
    float b2 = odd ? L1.w : L1.y;

    float ki0 = __ldg(ki0p);
    float ki1 = __ldg(ki1p);
    float ki0h  = 0.5f * ki0;
    float ki0_6 = ki0 * (1.0f / 6.0f);
    float k1s   = 0.5f * LN2_F * ki1;

    float A0, A1, A2, B0, B1, B2;
    kan_group(a0, a1, a2, ki0h, ki0_6, k1s, A0, A1, A2);
    kan_group(b0, b1, b2, ki0h, ki0_6, k1s, B0, B1, B2);

    // outputs already in natural order: floats 6t..6t+5 = A0 A1 A2 B0 B1 B2
    long long o = 3LL * t;
    out2[o + 0] = make_float2(A0, A1);
    out2[o + 1] = make_float2(A2, B0);
    out2[o + 2] = make_float2(B1, B2);
}

// Scalar fallback for groups not covered by the main kernel (defensive;
// unused for the benchmarked 4096x2048x3 shape which divides exactly).
__global__ void kan_stress_tail_kernel(const float* __restrict__ in, float* __restrict__ out,
                                       const float* __restrict__ ki0p, const float* __restrict__ ki1p,
                                       long long g0, long long n_groups) {
    long long g = g0 + blockIdx.x * (long long)blockDim.x + threadIdx.x;
    if (g >= n_groups) return;

    float ki0 = __ldg(ki0p);
    float ki1 = __ldg(ki1p);
    float ki0h  = 0.5f * ki0;
    float ki0_6 = ki0 * (1.0f / 6.0f);
    float k1s   = 0.5f * LN2_F * ki1;

    float s0 = in[3 * g + 0];
    float s1 = in[3 * g + 1];
    float s2 = in[3 * g + 2];
    float o0, o1, o2;
    kan_group(s0, s1, s2, ki0h, ki0_6, k1s, o0, o1, o2);
    out[3 * g + 0] = o0;
    out[3 * g + 1] = o1;
    out[3 * g + 2] = o2;
}

extern "C" void kernel_launch(void* const* d_in, const int* in_sizes, int n_in,
                              void* d_out, int out_size) {
    const float* strain = (const float*)d_in[0];
    const float* ki0    = (const float*)d_in[1];
    const float* ki1    = (const float*)d_in[2];
    float* out          = (float*)d_out;

    long long total_floats = in_sizes[0];     // B*T*3
    long long n_groups = total_floats / 3;

    // main kernel: thread t covers groups 2t,2t+1; reads f4 slots s,s+1
    // (highest float index read = 4*s+7 with s=(3t)>>1). Cap so reads stay
    // in bounds. Bench shape: total=25165824 -> nt=4194304 exact, no tail.
    long long nt = n_groups / 2;
    while (nt > 0) {
        long long last_s = (3 * (nt - 1)) >> 1;
        if (4 * last_s + 7 < total_floats) break;
        nt--;
    }

    if (nt > 0) {
        int block = 256;
        int grid = (int)((nt + block - 1) / block);
        kan_stress_f2_kernel<<<grid, block>>>(
            (const float4*)strain, (float2*)out, ki0, ki1, (int)nt);
    }

    long long g0 = 2 * nt;
    if (g0 < n_groups) {
        long long rem = n_groups - g0;
        int block = 128;
        int grid = (int)((rem + block - 1) / block);
        kan_stress_tail_kernel<<<grid, block>>>(strain, out, ki0, ki1, g0, n_groups);
    }
}